// round 17
// baseline (speedup 1.0000x reference)
#include <cuda_runtime.h>
#include <cstdint>
#include <cstddef>

#define NORB   9
#define NATOMS 384
#define NEDGES 6144
#define NKP    4
#define ALLN   (NATOMS * NORB)              // 3456
#define NFEAT  58
#define KELEM  (ALLN * ALLN)                // 11,943,936 floats per k-region
#define NCPLX  ((size_t)NKP * KELEM)        // 47,775,744
#define NITEM  (NEDGES + NATOMS)            // 6528
#define NSLOT  (2 * NEDGES + NATOMS)        // 12672
#define NPAIR  (NATOMS * NATOMS)            // 147456
#define TWO_PI 6.283185307179586f

// 64-byte chunks (16 floats)
#define CHUNKS ((int)(NCPLX / 16))          // 2,985,984
#define CPR    (ALLN / 16)                  // 216 chunks per row
#define CPK    (KELEM / 16)                 // 746,496 chunks per k-region
#define NWORDS (CHUNKS / 32)                // 93,312 bitmap words

#define NOWNB  640                          // owner blocks (grid-stride)
#define NFILLB 11664                        // 11664*1024 float4 = NCPLX/4 exact
#define NGRID  (NOWNB + NFILLB)

#define MZ_BLOCKS 918                       // 918*256 = 6528*36 exact
#define WLCAP  940032                       // >= 235008*4 possible first-sets
#define PLCAP  16384

// Feature factors (0.5 on l-diagonal orbital pairs, else 1.0)
__constant__ float cFACS[NFEAT] = {
    0.5f,
    1.f,1.f,1.f,
    1.f,1.f,1.f,1.f,1.f,
    0.5f,0.5f,0.5f,0.5f,0.5f,0.5f,0.5f,0.5f,0.5f,
    1.f,1.f,1.f,1.f,1.f,1.f,1.f,1.f,1.f,1.f,1.f,1.f,1.f,1.f,1.f,
    0.5f,0.5f,0.5f,0.5f,0.5f,0.5f,0.5f,0.5f,0.5f,0.5f,0.5f,0.5f,0.5f,
    0.5f,0.5f,0.5f,0.5f,0.5f,0.5f,0.5f,0.5f,0.5f,0.5f,0.5f,0.5f
};
// Direct pattern: f = fmap(r,c) or -1.
__constant__ signed char cFD[81] = {
     0,  1,  2,  3,  4,  5,  6,  7,  8,
    -1,  9, 10, 11, 18, 19, 20, 21, 22,
    -1, 12, 13, 14, 23, 24, 25, 26, 27,
    -1, 15, 16, 17, 28, 29, 30, 31, 32,
    -1, -1, -1, -1, 33, 34, 35, 36, 37,
    -1, -1, -1, -1, 38, 39, 40, 41, 42,
    -1, -1, -1, -1, 43, 44, 45, 46, 47,
    -1, -1, -1, -1, 48, 49, 50, 51, 52,
    -1, -1, -1, -1, 53, 54, 55, 56, 57
};
// Transposed pattern: cFT[r*9+c] = fmap(c,r).
__constant__ signed char cFT[81] = {
     0, -1, -1, -1, -1, -1, -1, -1, -1,
     1,  9, 12, 15, -1, -1, -1, -1, -1,
     2, 10, 13, 16, -1, -1, -1, -1, -1,
     3, 11, 14, 17, -1, -1, -1, -1, -1,
     4, 18, 23, 28, 33, 38, 43, 48, 53,
     5, 19, 24, 29, 34, 39, 44, 49, 54,
     6, 20, 25, 30, 35, 40, 45, 50, 55,
     7, 21, 26, 31, 36, 41, 46, 51, 56,
     8, 22, 27, 32, 37, 42, 47, 52, 57
};

// ---- static scratch (zero-initialized; self-resetting across replays) ----
__device__ int      g_head[NPAIR];   // pair -> slot+1, 0 = empty
__device__ int      g_next[NSLOT];   // chain links (slot+1 / 0)
__device__ unsigned g_bmw[NWORDS];   // touched-chunk bit per 64B chunk
__device__ int      g_wl[WLCAP];     // touched-chunk worklist (cids)
__device__ int      g_pl[PLCAP];     // touched-pair worklist
__device__ int      g_nwl, g_npl, g_done;

// slot encoding: [0,NEDGES) edge-direct, [NEDGES,2N) edge-transpose,
// [2N, 2N+NATOMS) onsite (both orientations).
__device__ __forceinline__ void push_pair(int pair, int slot) {
    const int old = atomicExch(&g_head[pair], slot + 1);
    g_next[slot] = old;
    if (old == 0) {
        const int p = atomicAdd(&g_npl, 1);
        if (p < PLCAP) g_pl[p] = pair;
    }
}

__device__ __forceinline__ void mark_chunk(int cid) {
    const unsigned bit = 1u << (cid & 31);
    const unsigned old = atomicOr(&g_bmw[cid >> 5], bit);
    if (!(old & bit)) {
        const int p = atomicAdd(&g_nwl, 1);
        if (p < WLCAP) g_wl[p] = cid;
    }
}

// Prep: thread = (item, k, row). Marks touched 64B chunks (+worklists) and,
// for the (k==0,row==0) subset, pushes the item's slots onto pair chains.
__global__ __launch_bounds__(256) void k_prep(const int* __restrict__ eidx) {
    const int t    = blockIdx.x * 256 + threadIdx.x;   // exact 235,008
    const int item = t / 36;
    const int rem  = t - item * 36;
    const int k    = rem / 9;
    const int row  = rem - k * 9;

    int a, b;
    if (item < NEDGES) { a = eidx[item]; b = eidx[NEDGES + item]; }
    else               { a = item - NEDGES; b = a; }
    if ((unsigned)a >= NATOMS || (unsigned)b >= NATOMS) return;

    if (rem == 0) {
        if (item < NEDGES) {
            push_pair(a * NATOMS + b, item);            // direct
            push_pair(b * NATOMS + a, NEDGES + item);   // transpose
        } else {
            push_pair(a * NATOMS + a, 2 * NEDGES + a);  // onsite (both)
        }
    }

    // mark chunks of block (a,b), row `row`
    {
        const int base = k * CPK + (a * NORB + row) * CPR;
        const int lo = (b * NORB) >> 4, hi = (b * NORB + 8) >> 4;
        mark_chunk(base + lo);
        if (hi != lo) mark_chunk(base + hi);
    }
    if (a != b) {   // mirror block (b,a)
        const int base = k * CPK + (b * NORB + row) * CPR;
        const int lo = (a * NORB) >> 4, hi = (a * NORB + 8) >> 4;
        mark_chunk(base + lo);
        if (hi != lo) mark_chunk(base + hi);
    }
}

// Main: owner blocks compute+store final values of touched chunks; fill
// blocks zero everything else (warp = 2KB = one bitmap word; near-memset
// instruction density) and self-clean the bitmap. Disjoint addresses -> no
// synchronization. Ticket-tail resets chains/counters for graph replay.
__global__ __launch_bounds__(256) void k_main(
    const float* __restrict__ hop,     // [E, 58]
    const float* __restrict__ ons,     // [N, 58]
    const float* __restrict__ kpts,    // [4, 3]
    const int*   __restrict__ eshift,  // [E, 3]
    float*       __restrict__ out)     // [4, 3456, 3456] float32 (real part)
{
    const int bid = blockIdx.x;
    const int tid = threadIdx.x;

    if (bid < NOWNB) {
        // ---------- owners: touched chunks ----------
        const int cnt = min(g_nwl, WLCAP);
        for (int idx = bid * 256 + tid; idx < cnt; idx += NOWNB * 256) {
            const int cid = g_wl[idx];
            const int k    = cid / CPK;
            const int rr   = cid - k * CPK;
            const int row  = rr / CPR;
            const int c16  = rr - row * CPR;
            const int rb   = row / NORB;
            const int r    = row - rb * NORB;
            const int col0 = c16 * 16;

            float acc[16];
            #pragma unroll
            for (int u = 0; u < 16; ++u) acc[u] = 0.f;

            const int cbS = col0 / NORB;
            const int cbE = (col0 + 15) / NORB;
            for (int cb = cbS; cb <= cbE; ++cb) {
                int h = g_head[rb * NATOMS + cb];
                const int cbase = cb * NORB;
                while (h) {
                    const int slot = h - 1;
                    const float* __restrict__ src;
                    int typ, e = -1;
                    if (slot < NEDGES)            { e = slot;          typ = 0; src = hop + (size_t)e * NFEAT; }
                    else if (slot < 2 * NEDGES)   { e = slot - NEDGES; typ = 1; src = hop + (size_t)e * NFEAT; }
                    else { typ = 2; src = ons + (size_t)(slot - 2 * NEDGES) * NFEAT; }

                    float ph = 1.f;
                    if (typ < 2) {
                        const float d = kpts[k * 3 + 0] * (float)eshift[e * 3 + 0]
                                      + kpts[k * 3 + 1] * (float)eshift[e * 3 + 1]
                                      + kpts[k * 3 + 2] * (float)eshift[e * 3 + 2];
                        ph = __cosf(TWO_PI * d);
                    }

                    #pragma unroll
                    for (int u = 0; u < 16; ++u) {
                        const int cc = col0 + u - cbase;     // col within block
                        if (cc < 0 || cc >= NORB) continue;
                        float v = 0.f;
                        if (typ != 1) {
                            const int f = cFD[r * NORB + cc];
                            if (f >= 0) v += cFACS[f] * src[f];
                        }
                        if (typ != 0) {
                            const int f = cFT[r * NORB + cc];
                            if (f >= 0) v += cFACS[f] * src[f];
                        }
                        acc[u] += v * ph;
                    }
                    h = g_next[slot];
                }
            }

            float4* __restrict__ dst = (float4*)out + (size_t)cid * 4;
            dst[0] = make_float4(acc[0],  acc[1],  acc[2],  acc[3]);
            dst[1] = make_float4(acc[4],  acc[5],  acc[6],  acc[7]);
            dst[2] = make_float4(acc[8],  acc[9],  acc[10], acc[11]);
            dst[3] = make_float4(acc[12], acc[13], acc[14], acc[15]);
        }
    } else {
        // ---------- fill: warp owns 2KB = one bitmap word ----------
        const int  bf    = bid - NOWNB;
        const int  w     = tid >> 5;
        const int  lane  = tid & 31;
        const int  widx  = bf * 8 + w;
        const unsigned word = g_bmw[widx];
        const size_t qb  = (size_t)bf * 1024 + w * 128;
        float4* __restrict__ out4 = (float4*)out;
        const float4 z = make_float4(0.f, 0.f, 0.f, 0.f);

        if (word == 0u) {
            #pragma unroll
            for (int u = 0; u < 4; ++u)
                out4[qb + u * 32 + lane] = z;        // 512B contiguous / instr
        } else {
            #pragma unroll
            for (int u = 0; u < 4; ++u)
                if (!((word >> (u * 8 + (lane >> 2))) & 1u))
                    out4[qb + u * 32 + lane] = z;
        }
        if (lane == 0) g_bmw[widx] = 0u;             // self-clean for replay
    }

    // ---------- ticket tail: last block resets chains & counters ----------
    __syncthreads();
    if (tid == 0) {
        const int old = atomicAdd(&g_done, 1);
        if (old == NGRID - 1) g_done = -2147483647;  // sentinel: I'm the last
    }
    __syncthreads();
    if (g_done == -2147483647) {
        const int np = min(g_npl, PLCAP);
        for (int i = tid; i < np; i += 256) g_head[g_pl[i]] = 0;
        __syncthreads();
        if (tid == 0) { g_nwl = 0; g_npl = 0; g_done = 0; }
    }
}

// ---- complex64 fallback (unused for the f32 output; kept for safety) ----
__constant__ unsigned char cROWS[NFEAT] = {
    0, 0,0,0, 0,0,0,0,0,
    1,1,1,2,2,2,3,3,3,
    1,1,1,1,1,2,2,2,2,2,3,3,3,3,3,
    4,4,4,4,4,5,5,5,5,5,6,6,6,6,6,7,7,7,7,7,8,8,8,8,8
};
__constant__ unsigned char cCOLS[NFEAT] = {
    0, 1,2,3, 4,5,6,7,8,
    1,2,3,1,2,3,1,2,3,
    4,5,6,7,8,4,5,6,7,8,4,5,6,7,8,
    4,5,6,7,8,4,5,6,7,8,4,5,6,7,8,4,5,6,7,8,4,5,6,7,8
};

__global__ void hr2hk_zero(uint4* __restrict__ out, size_t n_u4) {
    for (size_t i = (size_t)blockIdx.x * blockDim.x + threadIdx.x;
         i < n_u4; i += (size_t)gridDim.x * blockDim.x)
        out[i] = make_uint4(0u, 0u, 0u, 0u);
}

__global__ __launch_bounds__(256, 8) void hr2hk_scatter_cplx(
    const float* __restrict__ hop, const float* __restrict__ ons,
    const float* __restrict__ kpts, const int* __restrict__ eidx,
    const int* __restrict__ eshift, float* __restrict__ out)
{
    const int w = blockIdx.x;
    const int t = threadIdx.x;
    if (t >= NFEAT * NKP) return;
    const int f = t >> 2;
    const int k = t & 3;
    const bool is_edge = (w < NEDGES);

    int ai, aj;
    float pre, pim;
    if (is_edge) {
        ai = eidx[w];
        aj = eidx[NEDGES + w];
        const float d = kpts[k * 3 + 0] * (float)eshift[w * 3 + 0]
                      + kpts[k * 3 + 1] * (float)eshift[w * 3 + 1]
                      + kpts[k * 3 + 2] * (float)eshift[w * 3 + 2];
        float s, c;
        __sincosf(TWO_PI * d, &s, &c);
        pre = c; pim = -s;
    } else {
        ai = w - NEDGES; aj = ai; pre = 1.f; pim = 0.f;
    }
    if ((unsigned)ai >= NATOMS || (unsigned)aj >= NATOMS) return;

    const float* __restrict__ src =
        is_edge ? (hop + (size_t)w * NFEAT)
                : (ons + (size_t)(w - NEDGES) * NFEAT);
    const float val = cFACS[f] * src[f];
    const float re = val * pre, im = val * pim;
    const int r = ai * NORB + (int)cROWS[f];
    const int c = aj * NORB + (int)cCOLS[f];
    const size_t kbase = (size_t)k * KELEM;
    float* p0 = out + 2 * (kbase + (size_t)r * ALLN + c);
    float* p1 = out + 2 * (kbase + (size_t)c * ALLN + r);
    atomicAdd(p0 + 0, re);
    atomicAdd(p0 + 1, im);
    atomicAdd(p1 + 0, re);
    atomicAdd(p1 + 1, -im);
}

extern "C" void kernel_launch(void* const* d_in, const int* in_sizes, int n_in,
                              void* d_out, int out_size) {
    // Identify inputs by (pairwise-distinct) element counts, not position.
    const float* hop    = nullptr;
    const float* ons    = nullptr;
    const float* kpts   = nullptr;
    const int*   eidx   = nullptr;
    const int*   eshift = nullptr;

    for (int i = 0; i < n_in; ++i) {
        switch (in_sizes[i]) {
            case NEDGES * NFEAT: hop    = (const float*)d_in[i]; break;  // 356352
            case NATOMS * NFEAT: ons    = (const float*)d_in[i]; break;  // 22272
            case NKP * 3:        kpts   = (const float*)d_in[i]; break;  // 12
            case 2 * NEDGES:     eidx   = (const int*)d_in[i];   break;  // 12288
            case NEDGES * 3:     eshift = (const int*)d_in[i];   break;  // 18432
            default: break;
        }
    }
    if (!hop || !ons || !kpts || !eidx || !eshift) return;

    if ((long long)out_size == (long long)NCPLX) {
        // f32 real-part output: chains + chunk worklist, then owner-writes
        // for touched chunks and near-memset fill for everything else.
        k_prep<<<MZ_BLOCKS, 256>>>(eidx);
        k_main<<<NGRID, 256>>>(hop, ons, kpts, eshift, (float*)d_out);
    } else if ((long long)out_size == 2LL * (long long)NCPLX) {
        hr2hk_zero<<<8192, 256>>>((uint4*)d_out, NCPLX * 8 / 16);
        hr2hk_scatter_cplx<<<NEDGES + NATOMS, 256>>>(
            hop, ons, kpts, eidx, eshift, (float*)d_out);
    }
}